// round 13
// baseline (speedup 1.0000x reference)
#include <cuda_runtime.h>
#include <cuda_bf16.h>
#include <math.h>
#include <stdint.h>

#define NROWS 32768   // B*N
#define CCH   256
#define NSPLIT 64

// ---------------- scratch (device globals; no allocation allowed) ----------
__device__ float g_qsum[NROWS * CCH];
__device__ float g_gate[NROWS * CCH];
__device__ float g_ksum[NROWS * CCH];
__device__ float g_v   [NROWS * CCH];
__device__ float g_vloc[NROWS * CCH];     // layout [cc][32768] (transposed)
__device__ float g_Sp  [NSPLIT * 64 * 1024];
__device__ float g_S   [64 * 1024];

// split-bf16 operand arrays
__device__ __align__(128) uint16_t g_xh[NROWS * CCH];
__device__ __align__(128) uint16_t g_xl[NROWS * CCH];
__device__ __align__(128) uint16_t g_th[NROWS * CCH];
__device__ __align__(128) uint16_t g_tl[NROWS * CCH];
__device__ __align__(128) uint16_t g_bh[256 * 1024];
__device__ __align__(128) uint16_t g_bl[256 * 1024];
__device__ __align__(128) uint16_t g_ph[256 * 256];
__device__ __align__(128) uint16_t g_pl[256 * 256];

// ---------------- helpers ----------------------------------------------------
__device__ __forceinline__ float spow(float a, float p) {
    float aa = fabsf(a);
    if (aa == 0.0f) return 0.0f;
    if (p == 3.0f) return aa * aa * aa;
    return powf(aa, p);
}

__device__ __forceinline__ uint32_t smem_u32(const void* p) {
    uint32_t a;
    asm("{ .reg .u64 t; cvta.to.shared.u64 t, %1; cvt.u32.u64 %0, t; }" : "=r"(a) : "l"(p));
    return a;
}

__device__ __forceinline__ void ldsm_x4(uint32_t* r, uint32_t addr) {
    asm volatile("ldmatrix.sync.aligned.m8n8.x4.shared.b16 {%0,%1,%2,%3}, [%4];"
        : "=r"(r[0]), "=r"(r[1]), "=r"(r[2]), "=r"(r[3]) : "r"(addr));
}
__device__ __forceinline__ void ldsm_x4_t(uint32_t* r, uint32_t addr) {
    asm volatile("ldmatrix.sync.aligned.m8n8.x4.trans.shared.b16 {%0,%1,%2,%3}, [%4];"
        : "=r"(r[0]), "=r"(r[1]), "=r"(r[2]), "=r"(r[3]) : "r"(addr));
}
__device__ __forceinline__ void mma_bf16(float* c, const uint32_t* a,
                                         uint32_t b0, uint32_t b1) {
    asm volatile("mma.sync.aligned.m16n8k16.row.col.f32.bf16.bf16.f32 "
        "{%0,%1,%2,%3}, {%4,%5,%6,%7}, {%8,%9}, {%0,%1,%2,%3};"
        : "+f"(c[0]), "+f"(c[1]), "+f"(c[2]), "+f"(c[3])
        : "r"(a[0]), "r"(a[1]), "r"(a[2]), "r"(a[3]), "r"(b0), "r"(b1));
}

__device__ __forceinline__ void split2(float x, uint16_t& h, uint16_t& l) {
    __nv_bfloat16 hb = __float2bfloat16_rn(x);
    float hf = __bfloat162float(hb);
    __nv_bfloat16 lb = __float2bfloat16_rn(x - hf);
    h = __bfloat16_as_ushort(hb);
    l = __bfloat16_as_ushort(lb);
}

__device__ __forceinline__ void cp16(uint32_t saddr, const void* g) {
    asm volatile("cp.async.cg.shared.global [%0], [%1], 16;" :: "r"(saddr), "l"(g));
}
#define CP_COMMIT() asm volatile("cp.async.commit_group;" ::: "memory")
#define CP_WAIT(n)  asm volatile("cp.async.wait_group %0;" :: "n"(n) : "memory")

// ---------------- prep: split fp32 -> bf16 hi/lo (8 elems/thread) -----------
__global__ void __launch_bounds__(256)
k_split_x(const float* __restrict__ x)
{
    size_t base = ((size_t)blockIdx.x * 256 + threadIdx.x) * 8;
    float4 a0 = *(const float4*)(x + base);
    float4 a1 = *(const float4*)(x + base + 4);
    float av[8] = {a0.x, a0.y, a0.z, a0.w, a1.x, a1.y, a1.z, a1.w};
    uint16_t h[8], l[8];
#pragma unroll
    for (int i = 0; i < 8; i++) split2(av[i], h[i], l[i]);
    uint4 hv, lv;
    hv.x = (uint32_t)h[0] | ((uint32_t)h[1] << 16);
    hv.y = (uint32_t)h[2] | ((uint32_t)h[3] << 16);
    hv.z = (uint32_t)h[4] | ((uint32_t)h[5] << 16);
    hv.w = (uint32_t)h[6] | ((uint32_t)h[7] << 16);
    lv.x = (uint32_t)l[0] | ((uint32_t)l[1] << 16);
    lv.y = (uint32_t)l[2] | ((uint32_t)l[3] << 16);
    lv.z = (uint32_t)l[4] | ((uint32_t)l[5] << 16);
    lv.w = (uint32_t)l[6] | ((uint32_t)l[7] << 16);
    *(uint4*)(g_xh + base) = hv;
    *(uint4*)(g_xl + base) = lv;
}

__global__ void __launch_bounds__(256)
k_split_w(const float* __restrict__ Wqg, const float* __restrict__ Wkv,
          const float* __restrict__ Wproj)
{
    int idx = blockIdx.x * 256 + threadIdx.x;
    float4 a;
    uint16_t* dh; uint16_t* dl; size_t doff;
    if (idx < 65536) {
        int k = idx >> 8, n4 = (idx & 255) * 4;
        a = (n4 < 512) ? *(const float4*)(Wqg + (size_t)k * 512 + n4)
                       : *(const float4*)(Wkv + (size_t)k * 512 + n4 - 512);
        dh = g_bh; dl = g_bl; doff = (size_t)k * 1024 + n4;
    } else {
        int i2 = idx - 65536;
        int k = i2 >> 6, n4 = (i2 & 63) * 4;
        a = *(const float4*)(Wproj + (size_t)k * 256 + n4);
        dh = g_ph; dl = g_pl; doff = (size_t)k * 256 + n4;
    }
    uint16_t h[4], l[4];
    split2(a.x, h[0], l[0]); split2(a.y, h[1], l[1]);
    split2(a.z, h[2], l[2]); split2(a.w, h[3], l[3]);
    *(uint2*)(dh + doff) = make_uint2(
        (uint32_t)h[0] | ((uint32_t)h[1] << 16), (uint32_t)h[2] | ((uint32_t)h[3] << 16));
    *(uint2*)(dl + doff) = make_uint2(
        (uint32_t)l[0] | ((uint32_t)l[1] << 16), (uint32_t)l[2] | ((uint32_t)l[3] << 16));
}

// stage layout (bytes): A rows 80B-stride, B rows 272B-stride
#define ST_AH 0
#define ST_AL 10240
#define ST_BH 20480
#define ST_BL 29184
#define ST_SIZE 37888
#define OFF_PW  75776
#define SMEM_TOTAL 76288

// ---------------- split-bf16 mma.sync GEMM, 2-stage cp.async, 2 CTA/SM ------
__global__ void __launch_bounds__(256, 2)
k_gemm_mma(const float* __restrict__ power_p, const float* __restrict__ bias,
           float* __restrict__ out, int mode)
{
    extern __shared__ __align__(128) char smem[];
    const uint32_t sbase = smem_u32(smem);
    float* pwsh = (float*)(smem + OFF_PW);

    const int tid = threadIdx.x, wid = tid >> 5, lane = tid & 31;
    const int rowBase = blockIdx.y * 128;      // SLOW dim
    const int j0 = blockIdx.x * 128;           // FAST dim -> A L2 reuse

    const uint16_t* Ah = mode ? g_th : g_xh;
    const uint16_t* Al = mode ? g_tl : g_xl;
    const uint16_t* Bh = mode ? g_ph : g_bh;
    const uint16_t* Bl = mode ? g_pl : g_bl;
    const int ldB = mode ? 256 : 1024;

    const int seg = (mode == 0) ? (j0 >> 8) : -1;
    const bool dopow = (seg == 0 || seg == 2);
    if (dopow && tid < 128) {
        float pp = power_p[(j0 & 255) + tid];
        pwsh[tid] = 1.0f + 4.0f / (1.0f + expf(-pp));
    }

    float acc[4][4][4];
#pragma unroll
    for (int mt = 0; mt < 4; mt++)
#pragma unroll
        for (int nt = 0; nt < 4; nt++)
#pragma unroll
            for (int q = 0; q < 4; q++) acc[mt][nt][q] = 0.0f;

    const int wm = (wid >> 2) * 64;
    const int wn = (wid & 3) * 32;

    const int arow = tid >> 2, ach = (tid & 3) * 16;
    const int brow = tid >> 4, bch = (tid & 15) * 16;
    const size_t ag0 = (size_t)(rowBase + arow) * 256 + (ach >> 1);
    const size_t ag1 = (size_t)(rowBase + arow + 64) * 256 + (ach >> 1);
    const size_t bg0 = (size_t)brow * ldB + j0 + (bch >> 1);
    const size_t bg1 = (size_t)(brow + 16) * ldB + j0 + (bch >> 1);

    const uint32_t aoff = (uint32_t)((wm + (lane & 15)) * 80 + (lane >> 4) * 16);
    const uint32_t boff = (uint32_t)(((lane & 7) + 8 * ((lane >> 3) & 1)) * 272
                                     + (lane >> 4) * 16 + wn * 2);

#define LOAD_STAGE(st, kt) do { \
    uint32_t sb_ = sbase + (st) * ST_SIZE; \
    cp16(sb_ + ST_AH + arow * 80 + ach,         Ah + ag0 + (kt)); \
    cp16(sb_ + ST_AH + (arow + 64) * 80 + ach,  Ah + ag1 + (kt)); \
    cp16(sb_ + ST_AL + arow * 80 + ach,         Al + ag0 + (kt)); \
    cp16(sb_ + ST_AL + (arow + 64) * 80 + ach,  Al + ag1 + (kt)); \
    cp16(sb_ + ST_BH + brow * 272 + bch,        Bh + bg0 + (size_t)(kt) * ldB); \
    cp16(sb_ + ST_BH + (brow + 16) * 272 + bch, Bh + bg1 + (size_t)(kt) * ldB); \
    cp16(sb_ + ST_BL + brow * 272 + bch,        Bl + bg0 + (size_t)(kt) * ldB); \
    cp16(sb_ + ST_BL + (brow + 16) * 272 + bch, Bl + bg1 + (size_t)(kt) * ldB); \
} while (0)

    LOAD_STAGE(0, 0);
    CP_COMMIT();

    for (int i = 0; i < 8; i++) {
        if (i < 7) {
            LOAD_STAGE((i + 1) & 1, (i + 1) * 32);
            CP_COMMIT();
            CP_WAIT(1);
        } else {
            CP_WAIT(0);
        }
        __syncthreads();

        const uint32_t sb = sbase + (i & 1) * ST_SIZE;
#pragma unroll
        for (int ks = 0; ks < 2; ks++) {
            const uint32_t ao = sb + aoff + ks * 32;
            const uint32_t bo = sb + boff + ks * 16 * 272;
            uint32_t a4[4][4], bA[2][4], bB[2][4];
            // pass 0: Ah x Bh
#pragma unroll
            for (int mt = 0; mt < 4; mt++) ldsm_x4(a4[mt], ao + ST_AH + mt * 16 * 80);
#pragma unroll
            for (int np = 0; np < 2; np++) ldsm_x4_t(bA[np], bo + ST_BH + np * 32);
#pragma unroll
            for (int mt = 0; mt < 4; mt++)
#pragma unroll
                for (int nt = 0; nt < 4; nt++)
                    mma_bf16(acc[mt][nt], a4[mt],
                             bA[nt >> 1][(nt & 1) * 2], bA[nt >> 1][(nt & 1) * 2 + 1]);
            // pass 1: Ah x Bl
#pragma unroll
            for (int np = 0; np < 2; np++) ldsm_x4_t(bB[np], bo + ST_BL + np * 32);
#pragma unroll
            for (int mt = 0; mt < 4; mt++)
#pragma unroll
                for (int nt = 0; nt < 4; nt++)
                    mma_bf16(acc[mt][nt], a4[mt],
                             bB[nt >> 1][(nt & 1) * 2], bB[nt >> 1][(nt & 1) * 2 + 1]);
            // pass 2: Al x Bh (reuse bA)
#pragma unroll
            for (int mt = 0; mt < 4; mt++) ldsm_x4(a4[mt], ao + ST_AL + mt * 16 * 80);
#pragma unroll
            for (int mt = 0; mt < 4; mt++)
#pragma unroll
                for (int nt = 0; nt < 4; nt++)
                    mma_bf16(acc[mt][nt], a4[mt],
                             bA[nt >> 1][(nt & 1) * 2], bA[nt >> 1][(nt & 1) * 2 + 1]);
        }
        __syncthreads();
    }

    // ---- epilogue ----
    const int g = lane >> 2, tg = lane & 3;
    float* dst = nullptr;
    if (mode == 0)
        dst = (seg == 0) ? g_qsum : (seg == 1) ? g_gate : (seg == 2) ? g_ksum : g_v;

#pragma unroll
    for (int mt = 0; mt < 4; mt++) {
#pragma unroll
        for (int nt = 0; nt < 4; nt++) {
            int lc = wn + nt * 8 + 2 * tg;
            int row0 = rowBase + wm + mt * 16 + g;
            float v0 = acc[mt][nt][0], v1 = acc[mt][nt][1];
            float v2 = acc[mt][nt][2], v3 = acc[mt][nt][3];
            if (mode == 0) {
                int chan = (j0 & 255) + lc;
                if (dopow) {
                    float p0 = pwsh[lc], p1 = pwsh[lc + 1];
                    v0 = spow(v0, p0); v1 = spow(v1, p1);
                    v2 = spow(v2, p0); v3 = spow(v3, p1);
                }
                *(float2*)(dst + (size_t)row0 * 256 + chan)       = make_float2(v0, v1);
                *(float2*)(dst + (size_t)(row0 + 8) * 256 + chan) = make_float2(v2, v3);
            } else {
                int gcol = j0 + lc;
                float b0 = bias[gcol], b1 = bias[gcol + 1];
                *(float2*)(out + (size_t)row0 * 256 + gcol)       = make_float2(v0 + b0, v1 + b1);
                *(float2*)(out + (size_t)(row0 + 8) * 256 + gcol) = make_float2(v2 + b0, v3 + b1);
            }
        }
    }
}

// ---------------- fused mid kernel: kv_outer + conv, 512 threads -----------
// blocks [0,512):  S partials (R11 512-thread variant)
// blocks [512,768): depthwise conv, one (b,ch) per block, thread-halves x 4 h2
__global__ void __launch_bounds__(512)
k_mid(const float* __restrict__ dwc_w, const float* __restrict__ dwc_b)
{
    __shared__ float Sbuf[2 * 4640];       // conv: 2 x (68*68 pad 4640); kv: sK/sV

    const int tid = threadIdx.x;

    if (blockIdx.x < 512) {
        // ---------------- kv_outer ----------------
        float* sK = Sbuf;                   // 2048 floats
        float* sV = Sbuf + 2048;            // 2048 floats

        const int bk = blockIdx.x;
        const int b = bk & 7, s = bk >> 3;
        const int eh = tid & 1;
        const int d  = (tid >> 1) & 31;
        const int h  = tid >> 6;

        float4 acc4[4];
#pragma unroll
        for (int e = 0; e < 4; e++) acc4[e] = make_float4(0.f, 0.f, 0.f, 0.f);

        const size_t rbase = ((size_t)(b * 4096 + s * 64)) * 256;
        const int lr = tid >> 6, lc = (tid & 63) * 4;

        float4 pk = *(const float4*)(g_ksum + rbase + lr * 256 + lc);
        float4 pv = *(const float4*)(g_v    + rbase + lr * 256 + lc);

        for (int gloop = 0; gloop < 8; gloop++) {
            *(float4*)&sK[lr * 256 + lc] = pk;
            *(float4*)&sV[lr * 256 + lc] = pv;
            __syncthreads();

            if (gloop < 7) {
                const size_t gb = rbase + (size_t)(gloop + 1) * 2048;
                pk = *(const float4*)(g_ksum + gb + lr * 256 + lc);
                pv = *(const float4*)(g_v    + gb + lr * 256 + lc);
            }

#pragma unroll
            for (int r = 0; r < 8; r++) {
                float ks = sK[r * 256 + h * 32 + d];
                const float4* vr = (const float4*)&sV[r * 256 + h * 32 + eh * 16];
#pragma unroll
                for (int e = 0; e < 4; e++) {
                    float4 vv = vr[e];
                    acc4[e].x += ks * vv.x; acc4[e].y += ks * vv.y;
                    acc4[e].z += ks * vv.z; acc4[e].w += ks * vv.w;
                }
            }
            __syncthreads();
        }
        float4* dstp = (float4*)(g_Sp + ((size_t)(s * 64 + b * 8 + h)) * 1024
                                 + d * 32 + eh * 16);
#pragma unroll
        for (int e = 0; e < 4; e++) dstp[e] = acc4[e];
    } else {
        // ---------------- conv ----------------
        const int cb = blockIdx.x - 512;    // 0..255
        const int b = cb >> 5, ch = cb & 31;
        const int half = tid >> 8;          // 0/1
        const int ltid = tid & 255;
        float* Sin = Sbuf + half * 4640;

        float w[25];
#pragma unroll
        for (int t = 0; t < 25; t++) w[t] = dwc_w[ch * 25 + t];
        const float bias = dwc_b[ch];

        const int c  = ltid & 63;
        const int r0 = ltid >> 6;

#pragma unroll
        for (int hi = 0; hi < 4; hi++) {
            const int h2 = half * 4 + hi;
            const int base_n = (h2 << 9) | (ch << 4);
            __syncthreads();
            for (int idx = ltid; idx < 68 * 68; idx += 256) {
                int row = idx / 68;
                int col = idx - row * 68;
                int gr = row - 2, gc = col - 2;
                float v = 0.0f;
                if (gr >= 0 && gr < 64 && gc >= 0 && gc < 64) {
                    int n = base_n | (gr >> 2);
                    v = g_v[((size_t)(b * 4096 + n)) * 256 + (gr & 3) * 64 + gc];
                }
                Sin[idx] = v;
            }
            __syncthreads();

            float* dstc = g_vloc + (size_t)(ch * 8 + h2) * 32768 + b * 4096;
#pragma unroll
            for (int j = 0; j < 16; j++) {
                int r = r0 * 16 + j;
                float sum = bias;
#pragma unroll
                for (int kr = 0; kr < 5; kr++)
#pragma unroll
                    for (int kc = 0; kc < 5; kc++)
                        sum += w[kr * 5 + kc] * Sin[(r + kr) * 68 + (c + kc)];
                dstc[r * 64 + c] = sum;
            }
        }
    }
}

__global__ void k_reduceS()
{
    int i = blockIdx.x * 1024 + threadIdx.x;
    float s = 0.f;
#pragma unroll 16
    for (int p = 0; p < NSPLIT; p++) s += g_Sp[(size_t)p * 65536 + i];
    g_S[i] = s;
}

// ---------------- kernel 4: t = (q_sum @ S + v_loc) * gate -> split bf16 ----
__global__ void __launch_bounds__(256) k_combine()
{
    __shared__ float vlT[16 * 257];
    __shared__ float qsA[16 * 256];

    const int tid = threadIdx.x;
    const int r0 = blockIdx.x * 16;
    const int b  = r0 >> 12;
    const int h = tid >> 5, e = tid & 31;

    float Sc[32];
    const float* Sb = g_S + (size_t)b * 8192 + h * 1024 + e;
#pragma unroll
    for (int d = 0; d < 32; d++) Sc[d] = Sb[d * 32];

    {
        const int q = tid & 3;
#pragma unroll
        for (int t = 0; t < 4; t++) {
            int cc = t * 64 + (tid >> 2);
            float4 vv = *(const float4*)(g_vloc + (size_t)cc * 32768 + r0 + q * 4);
            vlT[(q * 4 + 0) * 257 + cc] = vv.x;
            vlT[(q * 4 + 1) * 257 + cc] = vv.y;
            vlT[(q * 4 + 2) * 257 + cc] = vv.z;
            vlT[(q * 4 + 3) * 257 + cc] = vv.w;
        }
    }
#pragma unroll
    for (int t = 0; t < 4; t++) {
        int idx = t * 256 + tid;
        int row = idx >> 6, c4 = (idx & 63) * 4;
        *(float4*)&qsA[row * 256 + c4] =
            *(const float4*)(g_qsum + (size_t)(r0 + row) * 256 + c4);
    }
    __syncthreads();

    const int c = tid;
    for (int ri = 0; ri < 16; ri++) {
        int r = r0 + ri;
        float ggv = g_gate[(size_t)r * 256 + c];
        const float* qr = &qsA[ri * 256 + h * 32];
        float acc = 0.f;
#pragma unroll
        for (int d = 0; d < 32; d++) acc += qr[d] * Sc[d];
        float val = (acc + vlT[ri * 257 + c]) * ggv;
        uint16_t hh, ll;
        split2(val, hh, ll);
        g_th[(size_t)r * 256 + c] = hh;
        g_tl[(size_t)r * 256 + c] = ll;
    }
}

// ---------------- launch -----------------------------------------------------
extern "C" void kernel_launch(void* const* d_in, const int* in_sizes, int n_in,
                              void* d_out, int out_size)
{
    const float* x     = (const float*)d_in[0];
    const float* Wqg   = (const float*)d_in[1];
    const float* Wkv   = (const float*)d_in[2];
    const float* Wproj = (const float*)d_in[3];
    const float* bproj = (const float*)d_in[4];
    const float* dwcw  = (const float*)d_in[5];
    const float* dwcb  = (const float*)d_in[6];
    const float* pp    = (const float*)d_in[7];
    float* out = (float*)d_out;

    cudaFuncSetAttribute(k_gemm_mma, cudaFuncAttributeMaxDynamicSharedMemorySize, SMEM_TOTAL);

    k_split_x<<<4096, 256>>>(x);
    k_split_w<<<320, 256>>>(Wqg, Wkv, Wproj);
    k_gemm_mma<<<dim3(8, 256), 256, SMEM_TOTAL>>>(pp, nullptr, nullptr, 0);
    k_mid     <<<768, 512>>>(dwcw, dwcb);          // fused kv_outer + conv
    k_reduceS <<<64, 1024>>>();
    k_combine <<<2048, 256>>>();
    k_gemm_mma<<<dim3(2, 256), 256, SMEM_TOTAL>>>(nullptr, bproj, out, 1);
}

// round 14
// speedup vs baseline: 1.0417x; 1.0417x over previous
#include <cuda_runtime.h>
#include <cuda_bf16.h>
#include <math.h>
#include <stdint.h>

#define NROWS 32768   // B*N
#define CCH   256
#define NSPLIT 64

// ---------------- scratch (device globals; no allocation allowed) ----------
__device__ float g_qsum[NROWS * CCH];
__device__ float g_gate[NROWS * CCH];
__device__ float g_ksum[NROWS * CCH];
__device__ float g_v   [NROWS * CCH];
__device__ float g_vloc[NROWS * CCH];     // layout [cc][32768] (transposed)
__device__ float g_Sp  [NSPLIT * 64 * 1024];
__device__ float g_S   [64 * 1024];

// split-bf16 operand arrays
__device__ __align__(128) uint16_t g_xh[NROWS * CCH];
__device__ __align__(128) uint16_t g_xl[NROWS * CCH];
__device__ __align__(128) uint16_t g_th[NROWS * CCH];
__device__ __align__(128) uint16_t g_tl[NROWS * CCH];
__device__ __align__(128) uint16_t g_bh[256 * 1024];
__device__ __align__(128) uint16_t g_bl[256 * 1024];
__device__ __align__(128) uint16_t g_ph[256 * 256];
__device__ __align__(128) uint16_t g_pl[256 * 256];

// ---------------- helpers ----------------------------------------------------
__device__ __forceinline__ float spow(float a, float p) {
    float aa = fabsf(a);
    if (aa == 0.0f) return 0.0f;
    if (p == 3.0f) return aa * aa * aa;
    return powf(aa, p);
}

__device__ __forceinline__ uint32_t smem_u32(const void* p) {
    uint32_t a;
    asm("{ .reg .u64 t; cvta.to.shared.u64 t, %1; cvt.u32.u64 %0, t; }" : "=r"(a) : "l"(p));
    return a;
}

__device__ __forceinline__ void ldsm_x4(uint32_t* r, uint32_t addr) {
    asm volatile("ldmatrix.sync.aligned.m8n8.x4.shared.b16 {%0,%1,%2,%3}, [%4];"
        : "=r"(r[0]), "=r"(r[1]), "=r"(r[2]), "=r"(r[3]) : "r"(addr));
}
__device__ __forceinline__ void ldsm_x4_t(uint32_t* r, uint32_t addr) {
    asm volatile("ldmatrix.sync.aligned.m8n8.x4.trans.shared.b16 {%0,%1,%2,%3}, [%4];"
        : "=r"(r[0]), "=r"(r[1]), "=r"(r[2]), "=r"(r[3]) : "r"(addr));
}
__device__ __forceinline__ void mma_bf16(float* c, const uint32_t* a,
                                         uint32_t b0, uint32_t b1) {
    asm volatile("mma.sync.aligned.m16n8k16.row.col.f32.bf16.bf16.f32 "
        "{%0,%1,%2,%3}, {%4,%5,%6,%7}, {%8,%9}, {%0,%1,%2,%3};"
        : "+f"(c[0]), "+f"(c[1]), "+f"(c[2]), "+f"(c[3])
        : "r"(a[0]), "r"(a[1]), "r"(a[2]), "r"(a[3]), "r"(b0), "r"(b1));
}

__device__ __forceinline__ void split2(float x, uint16_t& h, uint16_t& l) {
    __nv_bfloat16 hb = __float2bfloat16_rn(x);
    float hf = __bfloat162float(hb);
    __nv_bfloat16 lb = __float2bfloat16_rn(x - hf);
    h = __bfloat16_as_ushort(hb);
    l = __bfloat16_as_ushort(lb);
}

__device__ __forceinline__ void cp16(uint32_t saddr, const void* g) {
    asm volatile("cp.async.cg.shared.global [%0], [%1], 16;" :: "r"(saddr), "l"(g));
}
#define CP_COMMIT() asm volatile("cp.async.commit_group;" ::: "memory")
#define CP_WAIT(n)  asm volatile("cp.async.wait_group %0;" :: "n"(n) : "memory")

// ---------------- prep: split fp32 -> bf16 hi/lo (8 elems/thread) -----------
__global__ void __launch_bounds__(256)
k_split_x(const float* __restrict__ x)
{
    size_t base = ((size_t)blockIdx.x * 256 + threadIdx.x) * 8;
    float4 a0 = *(const float4*)(x + base);
    float4 a1 = *(const float4*)(x + base + 4);
    float av[8] = {a0.x, a0.y, a0.z, a0.w, a1.x, a1.y, a1.z, a1.w};
    uint16_t h[8], l[8];
#pragma unroll
    for (int i = 0; i < 8; i++) split2(av[i], h[i], l[i]);
    uint4 hv, lv;
    hv.x = (uint32_t)h[0] | ((uint32_t)h[1] << 16);
    hv.y = (uint32_t)h[2] | ((uint32_t)h[3] << 16);
    hv.z = (uint32_t)h[4] | ((uint32_t)h[5] << 16);
    hv.w = (uint32_t)h[6] | ((uint32_t)h[7] << 16);
    lv.x = (uint32_t)l[0] | ((uint32_t)l[1] << 16);
    lv.y = (uint32_t)l[2] | ((uint32_t)l[3] << 16);
    lv.z = (uint32_t)l[4] | ((uint32_t)l[5] << 16);
    lv.w = (uint32_t)l[6] | ((uint32_t)l[7] << 16);
    *(uint4*)(g_xh + base) = hv;
    *(uint4*)(g_xl + base) = lv;
}

__global__ void __launch_bounds__(256)
k_split_w(const float* __restrict__ Wqg, const float* __restrict__ Wkv,
          const float* __restrict__ Wproj)
{
    int idx = blockIdx.x * 256 + threadIdx.x;
    float4 a;
    uint16_t* dh; uint16_t* dl; size_t doff;
    if (idx < 65536) {
        int k = idx >> 8, n4 = (idx & 255) * 4;
        a = (n4 < 512) ? *(const float4*)(Wqg + (size_t)k * 512 + n4)
                       : *(const float4*)(Wkv + (size_t)k * 512 + n4 - 512);
        dh = g_bh; dl = g_bl; doff = (size_t)k * 1024 + n4;
    } else {
        int i2 = idx - 65536;
        int k = i2 >> 6, n4 = (i2 & 63) * 4;
        a = *(const float4*)(Wproj + (size_t)k * 256 + n4);
        dh = g_ph; dl = g_pl; doff = (size_t)k * 256 + n4;
    }
    uint16_t h[4], l[4];
    split2(a.x, h[0], l[0]); split2(a.y, h[1], l[1]);
    split2(a.z, h[2], l[2]); split2(a.w, h[3], l[3]);
    *(uint2*)(dh + doff) = make_uint2(
        (uint32_t)h[0] | ((uint32_t)h[1] << 16), (uint32_t)h[2] | ((uint32_t)h[3] << 16));
    *(uint2*)(dl + doff) = make_uint2(
        (uint32_t)l[0] | ((uint32_t)l[1] << 16), (uint32_t)l[2] | ((uint32_t)l[3] << 16));
}

// stage layout (bytes): A rows 80B-stride, B rows 272B-stride
#define ST_AH 0
#define ST_AL 10240
#define ST_BH 20480
#define ST_BL 29184
#define ST_SIZE 37888
#define OFF_PW  75776
#define SMEM_TOTAL 76288

// ---------------- split-bf16 mma.sync GEMM, 2-stage cp.async, 2 CTA/SM ------
__global__ void __launch_bounds__(256, 2)
k_gemm_mma(const float* __restrict__ power_p, const float* __restrict__ bias,
           float* __restrict__ out, int mode)
{
    extern __shared__ __align__(128) char smem[];
    const uint32_t sbase = smem_u32(smem);
    float* pwsh = (float*)(smem + OFF_PW);

    const int tid = threadIdx.x, wid = tid >> 5, lane = tid & 31;
    const int rowBase = blockIdx.y * 128;      // SLOW dim
    const int j0 = blockIdx.x * 128;           // FAST dim -> A L2 reuse

    const uint16_t* Ah = mode ? g_th : g_xh;
    const uint16_t* Al = mode ? g_tl : g_xl;
    const uint16_t* Bh = mode ? g_ph : g_bh;
    const uint16_t* Bl = mode ? g_pl : g_bl;
    const int ldB = mode ? 256 : 1024;

    const int seg = (mode == 0) ? (j0 >> 8) : -1;
    const bool dopow = (seg == 0 || seg == 2);
    if (dopow && tid < 128) {
        float pp = power_p[(j0 & 255) + tid];
        pwsh[tid] = 1.0f + 4.0f / (1.0f + expf(-pp));
    }

    float acc[4][4][4];
#pragma unroll
    for (int mt = 0; mt < 4; mt++)
#pragma unroll
        for (int nt = 0; nt < 4; nt++)
#pragma unroll
            for (int q = 0; q < 4; q++) acc[mt][nt][q] = 0.0f;

    const int wm = (wid >> 2) * 64;
    const int wn = (wid & 3) * 32;

    const int arow = tid >> 2, ach = (tid & 3) * 16;
    const int brow = tid >> 4, bch = (tid & 15) * 16;
    const size_t ag0 = (size_t)(rowBase + arow) * 256 + (ach >> 1);
    const size_t ag1 = (size_t)(rowBase + arow + 64) * 256 + (ach >> 1);
    const size_t bg0 = (size_t)brow * ldB + j0 + (bch >> 1);
    const size_t bg1 = (size_t)(brow + 16) * ldB + j0 + (bch >> 1);

    const uint32_t aoff = (uint32_t)((wm + (lane & 15)) * 80 + (lane >> 4) * 16);
    const uint32_t boff = (uint32_t)(((lane & 7) + 8 * ((lane >> 3) & 1)) * 272
                                     + (lane >> 4) * 16 + wn * 2);

#define LOAD_STAGE(st, kt) do { \
    uint32_t sb_ = sbase + (st) * ST_SIZE; \
    cp16(sb_ + ST_AH + arow * 80 + ach,         Ah + ag0 + (kt)); \
    cp16(sb_ + ST_AH + (arow + 64) * 80 + ach,  Ah + ag1 + (kt)); \
    cp16(sb_ + ST_AL + arow * 80 + ach,         Al + ag0 + (kt)); \
    cp16(sb_ + ST_AL + (arow + 64) * 80 + ach,  Al + ag1 + (kt)); \
    cp16(sb_ + ST_BH + brow * 272 + bch,        Bh + bg0 + (size_t)(kt) * ldB); \
    cp16(sb_ + ST_BH + (brow + 16) * 272 + bch, Bh + bg1 + (size_t)(kt) * ldB); \
    cp16(sb_ + ST_BL + brow * 272 + bch,        Bl + bg0 + (size_t)(kt) * ldB); \
    cp16(sb_ + ST_BL + (brow + 16) * 272 + bch, Bl + bg1 + (size_t)(kt) * ldB); \
} while (0)

    LOAD_STAGE(0, 0);
    CP_COMMIT();

    for (int i = 0; i < 8; i++) {
        if (i < 7) {
            LOAD_STAGE((i + 1) & 1, (i + 1) * 32);
            CP_COMMIT();
            CP_WAIT(1);
        } else {
            CP_WAIT(0);
        }
        __syncthreads();

        const uint32_t sb = sbase + (i & 1) * ST_SIZE;
#pragma unroll
        for (int ks = 0; ks < 2; ks++) {
            const uint32_t ao = sb + aoff + ks * 32;
            const uint32_t bo = sb + boff + ks * 16 * 272;
            uint32_t a4[4][4], bA[2][4], bB[2][4];
            // pass 0: Ah x Bh
#pragma unroll
            for (int mt = 0; mt < 4; mt++) ldsm_x4(a4[mt], ao + ST_AH + mt * 16 * 80);
#pragma unroll
            for (int np = 0; np < 2; np++) ldsm_x4_t(bA[np], bo + ST_BH + np * 32);
#pragma unroll
            for (int mt = 0; mt < 4; mt++)
#pragma unroll
                for (int nt = 0; nt < 4; nt++)
                    mma_bf16(acc[mt][nt], a4[mt],
                             bA[nt >> 1][(nt & 1) * 2], bA[nt >> 1][(nt & 1) * 2 + 1]);
            // pass 1: Ah x Bl
#pragma unroll
            for (int np = 0; np < 2; np++) ldsm_x4_t(bB[np], bo + ST_BL + np * 32);
#pragma unroll
            for (int mt = 0; mt < 4; mt++)
#pragma unroll
                for (int nt = 0; nt < 4; nt++)
                    mma_bf16(acc[mt][nt], a4[mt],
                             bB[nt >> 1][(nt & 1) * 2], bB[nt >> 1][(nt & 1) * 2 + 1]);
            // pass 2: Al x Bh (reuse bA)
#pragma unroll
            for (int mt = 0; mt < 4; mt++) ldsm_x4(a4[mt], ao + ST_AL + mt * 16 * 80);
#pragma unroll
            for (int mt = 0; mt < 4; mt++)
#pragma unroll
                for (int nt = 0; nt < 4; nt++)
                    mma_bf16(acc[mt][nt], a4[mt],
                             bA[nt >> 1][(nt & 1) * 2], bA[nt >> 1][(nt & 1) * 2 + 1]);
        }
        __syncthreads();
    }

    // ---- epilogue ----
    const int g = lane >> 2, tg = lane & 3;
    float* dst = nullptr;
    if (mode == 0)
        dst = (seg == 0) ? g_qsum : (seg == 1) ? g_gate : (seg == 2) ? g_ksum : g_v;

#pragma unroll
    for (int mt = 0; mt < 4; mt++) {
#pragma unroll
        for (int nt = 0; nt < 4; nt++) {
            int lc = wn + nt * 8 + 2 * tg;
            int row0 = rowBase + wm + mt * 16 + g;
            float v0 = acc[mt][nt][0], v1 = acc[mt][nt][1];
            float v2 = acc[mt][nt][2], v3 = acc[mt][nt][3];
            if (mode == 0) {
                int chan = (j0 & 255) + lc;
                if (dopow) {
                    float p0 = pwsh[lc], p1 = pwsh[lc + 1];
                    v0 = spow(v0, p0); v1 = spow(v1, p1);
                    v2 = spow(v2, p0); v3 = spow(v3, p1);
                }
                *(float2*)(dst + (size_t)row0 * 256 + chan)       = make_float2(v0, v1);
                *(float2*)(dst + (size_t)(row0 + 8) * 256 + chan) = make_float2(v2, v3);
            } else {
                int gcol = j0 + lc;
                float b0 = bias[gcol], b1 = bias[gcol + 1];
                *(float2*)(out + (size_t)row0 * 256 + gcol)       = make_float2(v0 + b0, v1 + b1);
                *(float2*)(out + (size_t)(row0 + 8) * 256 + gcol) = make_float2(v2 + b0, v3 + b1);
            }
        }
    }
}

// ---------------- kernel 2: S partials, 512 threads, low regs (R11 best) ----
__global__ void __launch_bounds__(512) k_kv_outer()
{
    __shared__ float sK[8 * 256];
    __shared__ float sV[8 * 256];

    const int b = blockIdx.x, s = blockIdx.y;
    const int tid = threadIdx.x;
    const int eh = tid & 1;
    const int d  = (tid >> 1) & 31;
    const int h  = tid >> 6;

    float4 acc4[4];
#pragma unroll
    for (int e = 0; e < 4; e++) acc4[e] = make_float4(0.f, 0.f, 0.f, 0.f);

    const size_t rbase = ((size_t)(b * 4096 + s * 64)) * 256;
    const int lr = tid >> 6, lc = (tid & 63) * 4;

    float4 pk = *(const float4*)(g_ksum + rbase + lr * 256 + lc);
    float4 pv = *(const float4*)(g_v    + rbase + lr * 256 + lc);

    for (int gloop = 0; gloop < 8; gloop++) {
        *(float4*)&sK[lr * 256 + lc] = pk;
        *(float4*)&sV[lr * 256 + lc] = pv;
        __syncthreads();

        if (gloop < 7) {
            const size_t gb = rbase + (size_t)(gloop + 1) * 2048;
            pk = *(const float4*)(g_ksum + gb + lr * 256 + lc);
            pv = *(const float4*)(g_v    + gb + lr * 256 + lc);
        }

#pragma unroll
        for (int r = 0; r < 8; r++) {
            float ks = sK[r * 256 + h * 32 + d];
            const float4* vr = (const float4*)&sV[r * 256 + h * 32 + eh * 16];
#pragma unroll
            for (int e = 0; e < 4; e++) {
                float4 vv = vr[e];
                acc4[e].x += ks * vv.x; acc4[e].y += ks * vv.y;
                acc4[e].z += ks * vv.z; acc4[e].w += ks * vv.w;
            }
        }
        __syncthreads();
    }
    float4* dstp = (float4*)(g_Sp + ((size_t)(s * 64 + b * 8 + h)) * 1024 + d * 32 + eh * 16);
#pragma unroll
    for (int e = 0; e < 4; e++) dstp[e] = acc4[e];
}

__global__ void k_reduceS()
{
    int i = blockIdx.x * 1024 + threadIdx.x;
    float s = 0.f;
#pragma unroll 16
    for (int p = 0; p < NSPLIT; p++) s += g_Sp[(size_t)p * 65536 + i];
    g_S[i] = s;
}

// ---------------- kernel 3: depthwise 5x5 conv, transposed output -----------
__global__ void __launch_bounds__(256)
k_conv(const float* __restrict__ dwc_w, const float* __restrict__ dwc_b)
{
    __shared__ float Sin[68 * 68];

    const int blk = blockIdx.x;          // 0..511
    const int half = blk & 1, ch = (blk >> 1) & 31, b = blk >> 6;
    const int tid = threadIdx.x;

    float w[25];
#pragma unroll
    for (int t = 0; t < 25; t++) w[t] = dwc_w[ch * 25 + t];
    const float bias = dwc_b[ch];

    const int c  = tid & 63;
    const int r0 = tid >> 6;

    for (int h2 = half * 4; h2 < half * 4 + 4; h2++) {
        const int base_n = (h2 << 9) | (ch << 4);
        __syncthreads();
        for (int idx = tid; idx < 68 * 68; idx += 256) {
            int row = idx / 68;
            int col = idx - row * 68;
            int gr = row - 2, gc = col - 2;
            float v = 0.0f;
            if (gr >= 0 && gr < 64 && gc >= 0 && gc < 64) {
                int n = base_n | (gr >> 2);
                v = g_v[((size_t)(b * 4096 + n)) * 256 + (gr & 3) * 64 + gc];
            }
            Sin[idx] = v;
        }
        __syncthreads();

        float* dstc = g_vloc + (size_t)(ch * 8 + h2) * 32768 + b * 4096;
#pragma unroll
        for (int j = 0; j < 16; j++) {
            int r = r0 * 16 + j;
            float sum = bias;
#pragma unroll
            for (int kr = 0; kr < 5; kr++)
#pragma unroll
                for (int kc = 0; kc < 5; kc++)
                    sum += w[kr * 5 + kc] * Sin[(r + kr) * 68 + (c + kc)];
            dstc[r * 64 + c] = sum;
        }
    }
}

// ---------------- kernel 4: t = (q_sum @ S + v_loc) * gate -> split bf16 ----
__global__ void __launch_bounds__(256) k_combine()
{
    __shared__ float vlT[16 * 257];
    __shared__ float qsA[16 * 256];

    const int tid = threadIdx.x;
    const int r0 = blockIdx.x * 16;
    const int b  = r0 >> 12;
    const int h = tid >> 5, e = tid & 31;

    float Sc[32];
    const float* Sb = g_S + (size_t)b * 8192 + h * 1024 + e;
#pragma unroll
    for (int d = 0; d < 32; d++) Sc[d] = Sb[d * 32];

    {
        const int q = tid & 3;
#pragma unroll
        for (int t = 0; t < 4; t++) {
            int cc = t * 64 + (tid >> 2);
            float4 vv = *(const float4*)(g_vloc + (size_t)cc * 32768 + r0 + q * 4);
            vlT[(q * 4 + 0) * 257 + cc] = vv.x;
            vlT[(q * 4 + 1) * 257 + cc] = vv.y;
            vlT[(q * 4 + 2) * 257 + cc] = vv.z;
            vlT[(q * 4 + 3) * 257 + cc] = vv.w;
        }
    }
#pragma unroll
    for (int t = 0; t < 4; t++) {
        int idx = t * 256 + tid;
        int row = idx >> 6, c4 = (idx & 63) * 4;
        *(float4*)&qsA[row * 256 + c4] =
            *(const float4*)(g_qsum + (size_t)(r0 + row) * 256 + c4);
    }
    __syncthreads();

    const int c = tid;
    for (int ri = 0; ri < 16; ri++) {
        int r = r0 + ri;
        float ggv = g_gate[(size_t)r * 256 + c];
        const float* qr = &qsA[ri * 256 + h * 32];
        float acc = 0.f;
#pragma unroll
        for (int d = 0; d < 32; d++) acc += qr[d] * Sc[d];
        float val = (acc + vlT[ri * 257 + c]) * ggv;
        uint16_t hh, ll;
        split2(val, hh, ll);
        g_th[(size_t)r * 256 + c] = hh;
        g_tl[(size_t)r * 256 + c] = ll;
    }
}

// ---------------- launch -----------------------------------------------------
extern "C" void kernel_launch(void* const* d_in, const int* in_sizes, int n_in,
                              void* d_out, int out_size)
{
    const float* x     = (const float*)d_in[0];
    const float* Wqg   = (const float*)d_in[1];
    const float* Wkv   = (const float*)d_in[2];
    const float* Wproj = (const float*)d_in[3];
    const float* bproj = (const float*)d_in[4];
    const float* dwcw  = (const float*)d_in[5];
    const float* dwcb  = (const float*)d_in[6];
    const float* pp    = (const float*)d_in[7];
    float* out = (float*)d_out;

    cudaFuncSetAttribute(k_gemm_mma, cudaFuncAttributeMaxDynamicSharedMemorySize, SMEM_TOTAL);

    k_split_x<<<4096, 256>>>(x);
    k_split_w<<<320, 256>>>(Wqg, Wkv, Wproj);
    k_gemm_mma<<<dim3(8, 256), 256, SMEM_TOTAL>>>(pp, nullptr, nullptr, 0);
    k_conv    <<<512, 256>>>(dwcw, dwcb);
    k_kv_outer<<<dim3(8, NSPLIT), 512>>>();
    k_reduceS <<<64, 1024>>>();
    k_combine <<<2048, 256>>>();
    k_gemm_mma<<<dim3(2, 256), 256, SMEM_TOTAL>>>(nullptr, bproj, out, 1);
}